// round 14
// baseline (speedup 1.0000x reference)
#include <cuda_runtime.h>
#include <cuda_fp16.h>
#include <math.h>
#include <stdint.h>

// Problem constants
#define T_TOK   2048
#define HDIM    1024
#define NEXP    16
#define IDIM    512
#define ISDIM   1024
#define TOPK    4
#define NGRP    4
#define EPG     4
#define SCALE_F 2.5f

#define BM 128
#define BN 128
#define BK 32
#define MAXSLOTS (8192 + NEXP*BM)    // 10240
#define SMS 40
#define TILEH (128 * SMS)
#define STAGE_BYTES (TILEH * 2)
#define NSTAGE 4
#define SMEM_TOTAL (2 * NSTAGE * STAGE_BYTES)   // 81920 B

// tile counts
#define N_EU 320
#define N_SU 128
#define N_ED 640
#define N_SD 128
#define NTILES (N_EU + N_SU + N_ED + N_SD)   // 1216
#define N_DN  (N_ED + N_SD)                  // 768

// cvt segmentation (float4 units)
#define C_X   524288u
#define C_W1  2097152u
#define C_W2  2097152u
#define C_WS  262144u
#define C_TOT (C_X + C_W1 + C_W2 + 2*C_WS)   // 5242880
#define CVT_PER_ITEM 4096u                    // f4 per item (64KB src)
#define NCVT_ITEMS ((C_TOT + CVT_PER_ITEM - 1) / CVT_PER_ITEM)   // 1280
#define NPHASEA (NCVT_ITEMS + T_TOK)

// ---------------- scratch ----------------
__device__ float  g_topw[T_TOK*TOPK];
__device__ int    g_tope[T_TOK*TOPK];
__device__ int    g_slotmap[T_TOK*TOPK];
__device__ int    g_list[MAXSLOTS];
__device__ int    g_cnt[NEXP];
__device__ int    g_cur[NEXP];
__device__ int    g_off[NEXP+1];

__device__ int    g_wqA;          // phase A queue
__device__ int    g_tix;          // tile queue
__device__ int    g_bar[3];       // grid barriers
__device__ int    g_done_eu[80];
__device__ int    g_done_su[16];
__device__ int    g_done_dn;

__device__ __half h_x  [(size_t)T_TOK * HDIM];
__device__ __half h_W1 [(size_t)NEXP * IDIM * HDIM];
__device__ __half h_W2 [(size_t)NEXP * HDIM * IDIM];
__device__ __half h_Ws1[(size_t)ISDIM * HDIM];
__device__ __half h_Ws2[(size_t)HDIM * ISDIM];

__device__ __half g_hid[(size_t)MAXSLOTS * IDIM];
__device__ float  g_y  [(size_t)MAXSLOTS * HDIM];
__device__ __half g_hs [(size_t)T_TOK * ISDIM];
__device__ float  g_ys [(size_t)T_TOK * HDIM];

// ---------------- helpers ----------------
__device__ __forceinline__ uint32_t smem_u32(const void* p) {
    uint32_t a;
    asm("{ .reg .u64 t; cvta.to.shared.u64 t, %1; cvt.u32.u64 %0, t; }" : "=r"(a) : "l"(p));
    return a;
}
__device__ __forceinline__ void cp16(uint32_t dst, const void* src) {
    asm volatile("cp.async.cg.shared.global [%0], [%1], 16;" :: "r"(dst), "l"(src));
}
__device__ __forceinline__ void ldsm_x4(uint32_t* r, uint32_t addr) {
    asm volatile("ldmatrix.sync.aligned.m8n8.x4.shared.b16 {%0,%1,%2,%3}, [%4];"
                 : "=r"(r[0]), "=r"(r[1]), "=r"(r[2]), "=r"(r[3]) : "r"(addr));
}
__device__ __forceinline__ void mma_f16(float* c, const uint32_t* a, const uint32_t* b) {
    asm volatile(
        "mma.sync.aligned.m16n8k16.row.col.f32.f16.f16.f32 "
        "{%0,%1,%2,%3}, {%4,%5,%6,%7}, {%8,%9}, {%0,%1,%2,%3};"
        : "+f"(c[0]), "+f"(c[1]), "+f"(c[2]), "+f"(c[3])
        : "r"(a[0]), "r"(a[1]), "r"(a[2]), "r"(a[3]), "r"(b[0]), "r"(b[1]));
}

// ---------------- init: reset ALL per-launch state ----------------
__global__ void init_kernel() {
    int i = blockIdx.x * 256 + threadIdx.x;
    if (i < NEXP) { g_cnt[i] = 0; g_cur[i] = 0; }
    if (i < MAXSLOTS) g_list[i] = -1;
    if (i == 0) { g_wqA = 0; g_tix = 0; g_done_dn = 0; }
    if (i < 3)  g_bar[i] = 0;
    if (i < 80) g_done_eu[i] = 0;
    if (i < 16) g_done_su[i] = 0;
}

// ---------------- grid barrier (all CTAs resident) ----------------
__device__ __forceinline__ void grid_barrier(int id, int grid) {
    __threadfence();            // release this thread's prior writes
    __syncthreads();
    if (threadIdx.x == 0) {
        atomicAdd(&g_bar[id], 1);
        while (atomicAdd(&g_bar[id], 0) < grid) __nanosleep(64);
    }
    __syncthreads();
    __threadfence();            // acquire
}

// ---------------- the mega kernel ----------------
__global__ void __launch_bounds__(256)
moe_mega(const float* __restrict__ xin,  const float* __restrict__ Wg,
         const float* __restrict__ bias, const float* __restrict__ W1f,
         const float* __restrict__ W2f,  const float* __restrict__ Ws1f,
         const float* __restrict__ Ws2f, float* __restrict__ out) {
    extern __shared__ __align__(16) __half dsm[];
    __shared__ int s_tix;
    __shared__ float slogS[NEXP];

    int tid  = threadIdx.x;
    int lane = tid & 31;
    int warp = tid >> 5;
    int grid = gridDim.x;

    // ================= Phase A: cvt + router work queue =================
    while (true) {
        if (tid == 0) s_tix = atomicAdd(&g_wqA, 1);
        __syncthreads();
        int it = s_tix;
        if (it >= NPHASEA) break;

        if (it < (int)NCVT_ITEMS) {
            // cvt item: 4096 float4
            uint32_t base = (uint32_t)it * CVT_PER_ITEM;
            #pragma unroll 4
            for (int q = 0; q < 16; q++) {
                uint32_t i = base + q * 256 + tid;
                if (i >= C_TOT) break;
                const float* s; __half* d; uint32_t off;
                if      (i < C_X)                      { s = xin;  d = h_x;   off = i; }
                else if (i < C_X + C_W1)               { s = W1f;  d = h_W1;  off = i - C_X; }
                else if (i < C_X + C_W1 + C_W2)        { s = W2f;  d = h_W2;  off = i - C_X - C_W1; }
                else if (i < C_X + C_W1 + C_W2 + C_WS) { s = Ws1f; d = h_Ws1; off = i - C_X - C_W1 - C_W2; }
                else                                   { s = Ws2f; d = h_Ws2; off = i - C_X - C_W1 - C_W2 - C_WS; }
                float4 v = *(const float4*)(s + (size_t)off * 4);
                __half2 lo = __floats2half2_rn(v.x, v.y);
                __half2 hi = __floats2half2_rn(v.z, v.w);
                uint2 u; u.x = *(uint32_t*)&lo; u.y = *(uint32_t*)&hi;
                *(uint2*)(d + (size_t)off * 4) = u;
            }
        } else {
            // router token (256 threads: 8 warps x 2 experts)
            int t = it - (int)NCVT_ITEMS;
            float* sx = (float*)dsm;
            const float* xr = xin + (size_t)t * HDIM;
            for (int i = tid; i < HDIM; i += 256) sx[i] = xr[i];
            __syncthreads();
            #pragma unroll
            for (int eo = 0; eo < 2; eo++) {
                int e = warp * 2 + eo;
                const float* w = Wg + (size_t)e * HDIM;
                float p = 0.f;
                for (int i = lane; i < HDIM; i += 32) p += sx[i] * w[i];
                #pragma unroll
                for (int o = 16; o; o >>= 1) p += __shfl_xor_sync(0xffffffffu, p, o);
                if (lane == 0) slogS[e] = p;
            }
            __syncthreads();
            if (tid == 0) {
                float sc[NEXP], ch[NEXP];
                #pragma unroll
                for (int e = 0; e < NEXP; e++) {
                    sc[e] = 1.f / (1.f + expf(-slogS[e]));
                    ch[e] = sc[e] + bias[e];
                }
                float gs[NGRP];
                #pragma unroll
                for (int g = 0; g < NGRP; g++) {
                    float m1 = -1e30f, m2 = -1e30f;
                    #pragma unroll
                    for (int k = 0; k < EPG; k++) {
                        float v = ch[g*EPG + k];
                        if (v > m1) { m2 = m1; m1 = v; } else if (v > m2) { m2 = v; }
                    }
                    gs[g] = m1 + m2;
                }
                int g1 = 0;
                for (int g = 1; g < NGRP; g++) if (gs[g] > gs[g1]) g1 = g;
                int g2 = -1;
                for (int g = 0; g < NGRP; g++) { if (g == g1) continue; if (g2 < 0 || gs[g] > gs[g2]) g2 = g; }
                float masked[NEXP];
                #pragma unroll
                for (int e = 0; e < NEXP; e++) {
                    int g = e >> 2;
                    masked[e] = (g == g1 || g == g2) ? ch[e] : 0.f;
                }
                int idx[TOPK]; float tw[TOPK]; float wsum = 0.f;
                #pragma unroll
                for (int j = 0; j < TOPK; j++) {
                    int b = 0;
                    for (int e = 1; e < NEXP; e++) if (masked[e] > masked[b]) b = e;
                    idx[j] = b; tw[j] = sc[b]; wsum += sc[b];
                    masked[b] = -1e30f;
                }
                float inv = SCALE_F / (wsum + 1e-20f);
                #pragma unroll
                for (int j = 0; j < TOPK; j++) {
                    g_topw[t*TOPK + j] = tw[j] * inv;
                    g_tope[t*TOPK + j] = idx[j];
                    atomicAdd(&g_cnt[idx[j]], 1);
                }
            }
            __syncthreads();   // sx reused by next item
        }
    }

    grid_barrier(0, grid);

    // ================= scan (one thread) =================
    if (blockIdx.x == 0 && tid == 0) {
        int o = 0;
        for (int e = 0; e < NEXP; e++) {
            g_off[e] = o;
            o += ((g_cnt[e] + BM - 1) / BM) * BM;
        }
        g_off[NEXP] = o;
    }

    grid_barrier(1, grid);

    // ================= fill (all threads) =================
    for (int t = blockIdx.x * 256 + tid; t < T_TOK; t += grid * 256) {
        for (int j = 0; j < TOPK; j++) {
            int e = g_tope[t*TOPK + j];
            int pos = atomicAdd(&g_cur[e], 1);
            int slot = g_off[e] + pos;
            g_list[slot] = t;
            g_slotmap[t*TOPK + j] = slot;
        }
    }

    grid_barrier(2, grid);

    // ================= tile queue (4 GEMMs) =================
    int wm = (warp & 1) * 64;
    int wn = (warp >> 1) * 32;

    uint32_t s0 = smem_u32(dsm);
    uint32_t aB[NSTAGE], bB[NSTAGE];
    #pragma unroll
    for (int s = 0; s < NSTAGE; s++) {
        aB[s] = s0 + s * STAGE_BYTES;
        bB[s] = s0 + (NSTAGE + s) * STAGE_BYTES;
    }

    int lrow = tid >> 1;
    int lcol = (tid & 1) * 16;
    uint32_t dOff = (uint32_t)(lrow * SMS + lcol) * 2;
    uint32_t aOff = (uint32_t)((wm + (lane & 15)) * SMS + (lane >> 4) * 8) * 2;
    uint32_t bOff = (uint32_t)((wn + ((lane >> 4) * 8) + (lane & 7)) * SMS + ((lane >> 3) & 1) * 8) * 2;

    while (true) {
        if (tid == 0) s_tix = atomicAdd(&g_tix, 1);
        __syncthreads();
        int tix = s_tix;
        if (tix >= NTILES) break;

        const __half *A, *W;
        void* C;
        int K, Ntot, relu, outH, gather;
        int row0, n0;
        int* doneCnt;
        int* waitCnt = 0; int waitNeed = 0;
        bool skip = false;

        if (tix < N_EU) {
            int rb = tix >> 2, bn = tix & 3;
            row0 = rb * BM; n0 = bn * BN;
            A = h_x; gather = 1; K = HDIM; Ntot = IDIM;
            C = (void*)g_hid; relu = 1; outH = 1;
            doneCnt = &g_done_eu[rb];
            W = h_W1;
            int tot = g_off[NEXP];
            if (row0 >= tot) skip = true;
            else {
                int eid = 0;
                while (row0 >= g_off[eid+1]) eid++;
                W = h_W1 + (size_t)eid * IDIM * HDIM;
            }
        } else if (tix < N_EU + N_SU) {
            int i2 = tix - N_EU; int rb = i2 >> 3, bn = i2 & 7;
            row0 = rb * BM; n0 = bn * BN;
            A = h_x; gather = 0; W = h_Ws1; K = HDIM; Ntot = ISDIM;
            C = (void*)g_hs; relu = 1; outH = 1;
            doneCnt = &g_done_su[rb];
        } else if (tix < N_EU + N_SU + N_ED) {
            int i2 = tix - N_EU - N_SU; int rb = i2 >> 3, bn = i2 & 7;
            row0 = rb * BM; n0 = bn * BN;
            A = g_hid; gather = 0; K = IDIM; Ntot = HDIM;
            C = (void*)g_y; relu = 0; outH = 0;
            doneCnt = &g_done_dn;
            W = h_W2;
            int tot = g_off[NEXP];
            if (row0 >= tot) skip = true;
            else {
                int eid = 0;
                while (row0 >= g_off[eid+1]) eid++;
                W = h_W2 + (size_t)eid * HDIM * IDIM;
                waitCnt = &g_done_eu[rb]; waitNeed = 4;
            }
        } else {
            int i2 = tix - N_EU - N_SU - N_ED; int rb = i2 >> 3, bn = i2 & 7;
            row0 = rb * BM; n0 = bn * BN;
            A = g_hs; gather = 0; W = h_Ws2; K = ISDIM; Ntot = HDIM;
            C = (void*)g_ys; relu = 0; outH = 0;
            doneCnt = &g_done_dn;
            waitCnt = &g_done_su[rb]; waitNeed = 8;
        }

        if (skip) {
            if (tid == 0) atomicAdd(doneCnt, 1);
            continue;
        }
        if (waitCnt) {
            if (tid == 0) {
                while (atomicAdd(waitCnt, 0) < waitNeed) __nanosleep(64);
                __threadfence();
            }
            __syncthreads();
        }

        const __half* arow;
        if (gather) {
            int tok = g_list[row0 + lrow];
            arow = A + (size_t)(tok >= 0 ? tok : 0) * K;
        } else {
            arow = A + (size_t)(row0 + lrow) * K;
        }
        const __half* brow = W + (size_t)(n0 + lrow) * K;

        float acc[4][4][4];
        #pragma unroll
        for (int i = 0; i < 4; i++)
            #pragma unroll
            for (int j = 0; j < 4; j++)
                #pragma unroll
                for (int q = 0; q < 4; q++) acc[i][j][q] = 0.f;

        int nt = K / BK;

        #pragma unroll
        for (int p = 0; p < 3; p++) {
            if (p < nt) {
                const __half* as = arow + p * BK + lcol;
                const __half* bs = brow + p * BK + lcol;
                cp16(aB[p] + dOff,      as);
                cp16(aB[p] + dOff + 16, as + 8);
                cp16(bB[p] + dOff,      bs);
                cp16(bB[p] + dOff + 16, bs + 8);
                asm volatile("cp.async.commit_group;");
            }
        }

        for (int kt = 0; kt < nt; kt++) {
            if (kt + 3 <= nt)       asm volatile("cp.async.wait_group 2;");
            else if (kt + 2 <= nt)  asm volatile("cp.async.wait_group 1;");
            else                    asm volatile("cp.async.wait_group 0;");
            __syncthreads();

            if (kt + 3 < nt) {
                int s = (kt + 3) % NSTAGE;
                const __half* as = arow + (kt + 3) * BK + lcol;
                const __half* bs = brow + (kt + 3) * BK + lcol;
                cp16(aB[s] + dOff,      as);
                cp16(aB[s] + dOff + 16, as + 8);
                cp16(bB[s] + dOff,      bs);
                cp16(bB[s] + dOff + 16, bs + 8);
                asm volatile("cp.async.commit_group;");
            }

            int buf = kt % NSTAGE;
            uint32_t aT = aB[buf], bT = bB[buf];
            #pragma unroll
            for (int ks = 0; ks < 2; ks++) {
                uint32_t kkB = (uint32_t)(ks * 16) * 2;
                uint32_t af[4][4], bf[4][2];
                #pragma unroll
                for (int mf = 0; mf < 4; mf++)
                    ldsm_x4(af[mf], aT + aOff + (uint32_t)(mf * 16 * SMS) * 2 + kkB);
                #pragma unroll
                for (int nfp = 0; nfp < 2; nfp++) {
                    uint32_t r[4];
                    ldsm_x4(r, bT + bOff + (uint32_t)(nfp * 16 * SMS) * 2 + kkB);
                    bf[nfp*2+0][0] = r[0]; bf[nfp*2+0][1] = r[1];
                    bf[nfp*2+1][0] = r[2]; bf[nfp*2+1][1] = r[3];
                }
                #pragma unroll
                for (int mf = 0; mf < 4; mf++)
                    #pragma unroll
                    for (int nf = 0; nf < 4; nf++)
                        mma_f16(acc[mf][nf], af[mf], bf[nf]);
            }
        }

        int gq = lane >> 2;
        int c2 = (lane & 3) * 2;
        #pragma unroll
        for (int mf = 0; mf < 4; mf++) {
            int r = row0 + wm + mf * 16 + gq;
            #pragma unroll
            for (int nf = 0; nf < 4; nf++) {
                int c = n0 + wn + nf * 8 + c2;
                float v0 = acc[mf][nf][0], v1 = acc[mf][nf][1];
                float v2 = acc[mf][nf][2], v3 = acc[mf][nf][3];
                if (relu) {
                    v0 = fmaxf(v0, 0.f); v0 *= v0;
                    v1 = fmaxf(v1, 0.f); v1 *= v1;
                    v2 = fmaxf(v2, 0.f); v2 *= v2;
                    v3 = fmaxf(v3, 0.f); v3 *= v3;
                }
                if (outH) {
                    __half2 lo = __floats2half2_rn(v0, v1);
                    __half2 hi = __floats2half2_rn(v2, v3);
                    *(uint32_t*)((__half*)C + (size_t) r      * Ntot + c) = *(uint32_t*)&lo;
                    *(uint32_t*)((__half*)C + (size_t)(r + 8) * Ntot + c) = *(uint32_t*)&hi;
                } else {
                    float2 lo; lo.x = v0; lo.y = v1;
                    float2 hi; hi.x = v2; hi.y = v3;
                    *(float2*)((float*)C + (size_t) r      * Ntot + c) = lo;
                    *(float2*)((float*)C + (size_t)(r + 8) * Ntot + c) = hi;
                }
            }
        }

        __threadfence();
        __syncthreads();
        if (tid == 0) atomicAdd(doneCnt, 1);
    }

    // ================= combine =================
    if (tid == 0) {
        while (atomicAdd(&g_done_dn, 0) < N_DN) __nanosleep(64);
        __threadfence();
    }
    __syncthreads();

    for (int t = blockIdx.x; t < T_TOK; t += grid) {
        int h = tid * 4;
        float4 o = *(const float4*)&g_ys[(size_t)t * HDIM + h];
        #pragma unroll
        for (int j = 0; j < TOPK; j++) {
            int slot = g_slotmap[t*TOPK + j];
            float w = g_topw[t*TOPK + j];
            float4 v = *(const float4*)&g_y[(size_t)slot * HDIM + h];
            o.x += w * v.x; o.y += w * v.y; o.z += w * v.z; o.w += w * v.w;
        }
        *(float4*)&out[(size_t)t * HDIM + h] = o;
    }
}

// ---------------- launch ----------------
extern "C" void kernel_launch(void* const* d_in, const int* in_sizes, int n_in,
                              void* d_out, int out_size) {
    const float *x = 0, *Wg = 0, *bias = 0, *W1 = 0, *W2 = 0, *Ws1 = 0, *Ws2 = 0;
    for (int i = 0; i < n_in; i++) {
        int sz = in_sizes[i];
        const float* p = (const float*)d_in[i];
        if      (sz == 2097152) { x = p; }
        else if (sz == 16384)   { Wg = p; }
        else if (sz == 16)      { bias = p; }
        else if (sz == 8388608) { if (!W1) W1 = p; else W2 = p; }
        else if (sz == 1048576) { if (!Ws1) Ws1 = p; else Ws2 = p; }
    }
    if (!x || !Wg || !bias || !W1 || !W2 || !Ws1 || !Ws2) {
        x = (const float*)d_in[0]; Wg = (const float*)d_in[1]; bias = (const float*)d_in[2];
        W1 = (const float*)d_in[3]; W2 = (const float*)d_in[4];
        Ws1 = (const float*)d_in[5]; Ws2 = (const float*)d_in[6];
    }
    float* out = (float*)d_out;

    cudaFuncSetAttribute(moe_mega, cudaFuncAttributeMaxDynamicSharedMemorySize, SMEM_TOTAL);

    int smCount = 148, occ = 1;
    cudaDeviceGetAttribute(&smCount, cudaDevAttrMultiProcessorCount, 0);
    cudaOccupancyMaxActiveBlocksPerMultiprocessor(&occ, moe_mega, 256, SMEM_TOTAL);
    if (occ < 1) occ = 1;
    int grid = smCount * occ;

    init_kernel<<<(MAXSLOTS + 255) / 256, 256>>>();
    moe_mega<<<grid, 256, SMEM_TOTAL>>>(x, Wg, bias, W1, W2, Ws1, Ws2, out);
}

// round 15
// speedup vs baseline: 1.8197x; 1.8197x over previous
#include <cuda_runtime.h>
#include <cuda_fp16.h>
#include <math.h>
#include <stdint.h>

// Problem constants
#define T_TOK   2048
#define HDIM    1024
#define NEXP    16
#define IDIM    512
#define ISDIM   1024
#define TOPK    4
#define NGRP    4
#define EPG     4
#define SCALE_F 2.5f

#define BM 128
#define BN 128
#define BK 32
#define MAXSLOTS (8192 + NEXP*BM)    // 10240
#define SMS 40
#define TILEH (128 * SMS)
#define STAGE_BYTES (TILEH * 2)
#define NSTAGE 4
#define SMEM_TOTAL (2 * NSTAGE * STAGE_BYTES)   // 81920 B

// tile counts
#define N_EU 320
#define N_SU 128
#define N_ED 640
#define N_SD 128
#define NTILES (N_EU + N_SU + N_ED + N_SD)   // 1216
#define N_DN  (N_ED + N_SD)                  // 768

// cvt segmentation (float4 units)
#define C_X   524288u
#define C_W1  2097152u
#define C_W2  2097152u
#define C_WS  262144u
#define C_TOT (C_X + C_W1 + C_W2 + 2*C_WS)   // 5242880

// ---------------- scratch ----------------
__device__ float  g_topw[T_TOK*TOPK];
__device__ int    g_tope[T_TOK*TOPK];
__device__ int    g_slotmap[T_TOK*TOPK];
__device__ int    g_list[MAXSLOTS];
__device__ int    g_cnt[NEXP];
__device__ int    g_off[NEXP+1];

__device__ int    g_tix;
__device__ int    g_done_eu[80];
__device__ int    g_done_su[16];
__device__ int    g_done_dn;

__device__ __half h_x  [(size_t)T_TOK * HDIM];
__device__ __half h_W1 [(size_t)NEXP * IDIM * HDIM];
__device__ __half h_W2 [(size_t)NEXP * HDIM * IDIM];
__device__ __half h_Ws1[(size_t)ISDIM * HDIM];
__device__ __half h_Ws2[(size_t)HDIM * ISDIM];

__device__ __half g_hid[(size_t)MAXSLOTS * IDIM];
__device__ float  g_y  [(size_t)MAXSLOTS * HDIM];
__device__ __half g_hs [(size_t)T_TOK * ISDIM];
__device__ float  g_ys [(size_t)T_TOK * HDIM];

// ---------------- helpers ----------------
__device__ __forceinline__ uint32_t smem_u32(const void* p) {
    uint32_t a;
    asm("{ .reg .u64 t; cvta.to.shared.u64 t, %1; cvt.u32.u64 %0, t; }" : "=r"(a) : "l"(p));
    return a;
}
__device__ __forceinline__ void cp16(uint32_t dst, const void* src) {
    asm volatile("cp.async.cg.shared.global [%0], [%1], 16;" :: "r"(dst), "l"(src));
}
__device__ __forceinline__ void ldsm_x4(uint32_t* r, uint32_t addr) {
    asm volatile("ldmatrix.sync.aligned.m8n8.x4.shared.b16 {%0,%1,%2,%3}, [%4];"
                 : "=r"(r[0]), "=r"(r[1]), "=r"(r[2]), "=r"(r[3]) : "r"(addr));
}
__device__ __forceinline__ void mma_f16(float* c, const uint32_t* a, const uint32_t* b) {
    asm volatile(
        "mma.sync.aligned.m16n8k16.row.col.f32.f16.f16.f32 "
        "{%0,%1,%2,%3}, {%4,%5,%6,%7}, {%8,%9}, {%0,%1,%2,%3};"
        : "+f"(c[0]), "+f"(c[1]), "+f"(c[2]), "+f"(c[3])
        : "r"(a[0]), "r"(a[1]), "r"(a[2]), "r"(a[3]), "r"(b[0]), "r"(b[1]));
}

// ---------------- init + cvt (one kernel) ----------------
__global__ void init_cvt(const float* __restrict__ x,  const float* __restrict__ W1,
                         const float* __restrict__ W2, const float* __restrict__ Ws1,
                         const float* __restrict__ Ws2) {
    int gi = blockIdx.x * 256 + threadIdx.x;
    // state resets
    if (gi < NEXP) g_cnt[gi] = 0;
    if (gi < MAXSLOTS) g_list[gi] = -1;
    if (gi == 0) { g_tix = 0; g_done_dn = 0; }
    if (gi < 80) g_done_eu[gi] = 0;
    if (gi < 16) g_done_su[gi] = 0;
    // grid-stride fp32 -> fp16 conversion
    int stride = gridDim.x * 256;
    for (uint32_t i = gi; i < C_TOT; i += stride) {
        const float* s; __half* d; uint32_t off;
        if      (i < C_X)                      { s = x;   d = h_x;   off = i; }
        else if (i < C_X + C_W1)               { s = W1;  d = h_W1;  off = i - C_X; }
        else if (i < C_X + C_W1 + C_W2)        { s = W2;  d = h_W2;  off = i - C_X - C_W1; }
        else if (i < C_X + C_W1 + C_W2 + C_WS) { s = Ws1; d = h_Ws1; off = i - C_X - C_W1 - C_W2; }
        else                                   { s = Ws2; d = h_Ws2; off = i - C_X - C_W1 - C_W2 - C_WS; }
        float4 v = *(const float4*)(s + (size_t)off * 4);
        __half2 lo = __floats2half2_rn(v.x, v.y);
        __half2 hi = __floats2half2_rn(v.z, v.w);
        uint2 u; u.x = *(uint32_t*)&lo; u.y = *(uint32_t*)&hi;
        *(uint2*)(d + (size_t)off * 4) = u;
    }
}

// ---------------- router ----------------
__global__ void router_kernel(const float* __restrict__ x,
                              const float* __restrict__ Wg,
                              const float* __restrict__ bias) {
    int t = blockIdx.x;
    __shared__ float sx[HDIM];
    __shared__ float slog[NEXP];
    const float* xr = x + (size_t)t * HDIM;
    for (int i = threadIdx.x; i < HDIM; i += 128) sx[i] = xr[i];
    __syncthreads();
    int warp = threadIdx.x >> 5, lane = threadIdx.x & 31;
    for (int eo = 0; eo < 4; eo++) {
        int e = warp * 4 + eo;
        const float* w = Wg + (size_t)e * HDIM;
        float p = 0.f;
        for (int i = lane; i < HDIM; i += 32) p += sx[i] * w[i];
        #pragma unroll
        for (int o = 16; o; o >>= 1) p += __shfl_xor_sync(0xffffffffu, p, o);
        if (lane == 0) slog[e] = p;
    }
    __syncthreads();
    if (threadIdx.x == 0) {
        float sc[NEXP], ch[NEXP];
        #pragma unroll
        for (int e = 0; e < NEXP; e++) {
            sc[e] = 1.f / (1.f + expf(-slog[e]));
            ch[e] = sc[e] + bias[e];
        }
        float gs[NGRP];
        #pragma unroll
        for (int g = 0; g < NGRP; g++) {
            float m1 = -1e30f, m2 = -1e30f;
            #pragma unroll
            for (int k = 0; k < EPG; k++) {
                float v = ch[g*EPG + k];
                if (v > m1) { m2 = m1; m1 = v; } else if (v > m2) { m2 = v; }
            }
            gs[g] = m1 + m2;
        }
        int g1 = 0;
        for (int g = 1; g < NGRP; g++) if (gs[g] > gs[g1]) g1 = g;
        int g2 = -1;
        for (int g = 0; g < NGRP; g++) { if (g == g1) continue; if (g2 < 0 || gs[g] > gs[g2]) g2 = g; }
        float masked[NEXP];
        #pragma unroll
        for (int e = 0; e < NEXP; e++) {
            int g = e >> 2;
            masked[e] = (g == g1 || g == g2) ? ch[e] : 0.f;
        }
        int idx[TOPK]; float tw[TOPK]; float wsum = 0.f;
        #pragma unroll
        for (int j = 0; j < TOPK; j++) {
            int b = 0;
            for (int e = 1; e < NEXP; e++) if (masked[e] > masked[b]) b = e;
            idx[j] = b; tw[j] = sc[b]; wsum += sc[b];
            masked[b] = -1e30f;
        }
        float inv = SCALE_F / (wsum + 1e-20f);
        #pragma unroll
        for (int j = 0; j < TOPK; j++) {
            g_topw[t*TOPK + j] = tw[j] * inv;
            g_tope[t*TOPK + j] = idx[j];
            atomicAdd(&g_cnt[idx[j]], 1);
        }
    }
}

// ---------------- scan + fill (single block) ----------------
__global__ void scan_fill() {
    __shared__ int s_cur[NEXP];
    int tid = threadIdx.x;
    if (tid == 0) {
        int o = 0;
        for (int e = 0; e < NEXP; e++) {
            g_off[e] = o;
            o += ((g_cnt[e] + BM - 1) / BM) * BM;
        }
        g_off[NEXP] = o;
    }
    if (tid < NEXP) s_cur[tid] = 0;
    __syncthreads();
    for (int t = tid; t < T_TOK; t += 256) {
        for (int j = 0; j < TOPK; j++) {
            int e = g_tope[t*TOPK + j];
            int pos = atomicAdd(&s_cur[e], 1);
            int slot = g_off[e] + pos;
            g_list[slot] = t;
            g_slotmap[t*TOPK + j] = slot;
        }
    }
}

// ---------------- persistent MoE kernel: 4 GEMMs + combine (R13-proven) ----------------
__global__ void __launch_bounds__(256)
moe_persistent(float* __restrict__ out) {
    extern __shared__ __align__(16) __half dsm[];
    __shared__ int s_tix;

    int tid  = threadIdx.x;
    int lane = tid & 31;
    int warp = tid >> 5;
    int wm = (warp & 1) * 64;
    int wn = (warp >> 1) * 32;

    uint32_t s0 = smem_u32(dsm);
    uint32_t aB[NSTAGE], bB[NSTAGE];
    #pragma unroll
    for (int s = 0; s < NSTAGE; s++) {
        aB[s] = s0 + s * STAGE_BYTES;
        bB[s] = s0 + (NSTAGE + s) * STAGE_BYTES;
    }

    int lrow = tid >> 1;
    int lcol = (tid & 1) * 16;
    uint32_t dOff = (uint32_t)(lrow * SMS + lcol) * 2;
    uint32_t aOff = (uint32_t)((wm + (lane & 15)) * SMS + (lane >> 4) * 8) * 2;
    uint32_t bOff = (uint32_t)((wn + ((lane >> 4) * 8) + (lane & 7)) * SMS + ((lane >> 3) & 1) * 8) * 2;

    while (true) {
        if (tid == 0) s_tix = atomicAdd(&g_tix, 1);
        __syncthreads();
        int tix = s_tix;
        if (tix >= NTILES) break;

        const __half *A, *W;
        void* C;
        int K, Ntot, relu, outH, gather;
        int row0, n0;
        int* doneCnt;
        int* waitCnt = 0; int waitNeed = 0;
        bool skip = false;

        if (tix < N_EU) {
            int rb = tix >> 2, bn = tix & 3;
            row0 = rb * BM; n0 = bn * BN;
            A = h_x; gather = 1; K = HDIM; Ntot = IDIM;
            C = (void*)g_hid; relu = 1; outH = 1;
            doneCnt = &g_done_eu[rb];
            W = h_W1;
            int tot = g_off[NEXP];
            if (row0 >= tot) skip = true;
            else {
                int eid = 0;
                while (row0 >= g_off[eid+1]) eid++;
                W = h_W1 + (size_t)eid * IDIM * HDIM;
            }
        } else if (tix < N_EU + N_SU) {
            int i2 = tix - N_EU; int rb = i2 >> 3, bn = i2 & 7;
            row0 = rb * BM; n0 = bn * BN;
            A = h_x; gather = 0; W = h_Ws1; K = HDIM; Ntot = ISDIM;
            C = (void*)g_hs; relu = 1; outH = 1;
            doneCnt = &g_done_su[rb];
        } else if (tix < N_EU + N_SU + N_ED) {
            int i2 = tix - N_EU - N_SU; int rb = i2 >> 3, bn = i2 & 7;
            row0 = rb * BM; n0 = bn * BN;
            A = g_hid; gather = 0; K = IDIM; Ntot = HDIM;
            C = (void*)g_y; relu = 0; outH = 0;
            doneCnt = &g_done_dn;
            W = h_W2;
            int tot = g_off[NEXP];
            if (row0 >= tot) skip = true;
            else {
                int eid = 0;
                while (row0 >= g_off[eid+1]) eid++;
                W = h_W2 + (size_t)eid * HDIM * IDIM;
                waitCnt = &g_done_eu[rb]; waitNeed = 4;
            }
        } else {
            int i2 = tix - N_EU - N_SU - N_ED; int rb = i2 >> 3, bn = i2 & 7;
            row0 = rb * BM; n0 = bn * BN;
            A = g_hs; gather = 0; W = h_Ws2; K = ISDIM; Ntot = HDIM;
            C = (void*)g_ys; relu = 0; outH = 0;
            doneCnt = &g_done_dn;
            waitCnt = &g_done_su[rb]; waitNeed = 8;
        }

        if (skip) {
            if (tid == 0) atomicAdd(doneCnt, 1);
            continue;
        }
        if (waitCnt) {
            if (tid == 0) {
                while (atomicAdd(waitCnt, 0) < waitNeed) __nanosleep(64);
                __threadfence();
            }
            __syncthreads();
        }

        const __half* arow;
        if (gather) {
            int tok = g_list[row0 + lrow];
            arow = A + (size_t)(tok >= 0 ? tok : 0) * K;
        } else {
            arow = A + (size_t)(row0 + lrow) * K;
        }
        const __half* brow = W + (size_t)(n0 + lrow) * K;

        float acc[4][4][4];
        #pragma unroll
        for (int i = 0; i < 4; i++)
            #pragma unroll
            for (int j = 0; j < 4; j++)
                #pragma unroll
                for (int q = 0; q < 4; q++) acc[i][j][q] = 0.f;

        int nt = K / BK;

        #pragma unroll
        for (int p = 0; p < 3; p++) {
            if (p < nt) {
                const __half* as = arow + p * BK + lcol;
                const __half* bs = brow + p * BK + lcol;
                cp16(aB[p] + dOff,      as);
                cp16(aB[p] + dOff + 16, as + 8);
                cp16(bB[p] + dOff,      bs);
                cp16(bB[p] + dOff + 16, bs + 8);
                asm volatile("cp.async.commit_group;");
            }
        }

        for (int kt = 0; kt < nt; kt++) {
            if (kt + 3 <= nt)       asm volatile("cp.async.wait_group 2;");
            else if (kt + 2 <= nt)  asm volatile("cp.async.wait_group 1;");
            else                    asm volatile("cp.async.wait_group 0;");
            __syncthreads();

            if (kt + 3 < nt) {
                int s = (kt + 3) % NSTAGE;
                const __half* as = arow + (kt + 3) * BK + lcol;
                const __half* bs = brow + (kt + 3) * BK + lcol;
                cp16(aB[s] + dOff,      as);
                cp16(aB[s] + dOff + 16, as + 8);
                cp16(bB[s] + dOff,      bs);
                cp16(bB[s] + dOff + 16, bs + 8);
                asm volatile("cp.async.commit_group;");
            }

            int buf = kt % NSTAGE;
            uint32_t aT = aB[buf], bT = bB[buf];
            #pragma unroll
            for (int ks = 0; ks < 2; ks++) {
                uint32_t kkB = (uint32_t)(ks * 16) * 2;
                uint32_t af[4][4], bf[4][2];
                #pragma unroll
                for (int mf = 0; mf < 4; mf++)
                    ldsm_x4(af[mf], aT + aOff + (uint32_t)(mf * 16 * SMS) * 2 + kkB);
                #pragma unroll
                for (int nfp = 0; nfp < 2; nfp++) {
                    uint32_t r[4];
                    ldsm_x4(r, bT + bOff + (uint32_t)(nfp * 16 * SMS) * 2 + kkB);
                    bf[nfp*2+0][0] = r[0]; bf[nfp*2+0][1] = r[1];
                    bf[nfp*2+1][0] = r[2]; bf[nfp*2+1][1] = r[3];
                }
                #pragma unroll
                for (int mf = 0; mf < 4; mf++)
                    #pragma unroll
                    for (int nf = 0; nf < 4; nf++)
                        mma_f16(acc[mf][nf], af[mf], bf[nf]);
            }
        }

        int gq = lane >> 2;
        int c2 = (lane & 3) * 2;
        #pragma unroll
        for (int mf = 0; mf < 4; mf++) {
            int r = row0 + wm + mf * 16 + gq;
            #pragma unroll
            for (int nf = 0; nf < 4; nf++) {
                int c = n0 + wn + nf * 8 + c2;
                float v0 = acc[mf][nf][0], v1 = acc[mf][nf][1];
                float v2 = acc[mf][nf][2], v3 = acc[mf][nf][3];
                if (relu) {
                    v0 = fmaxf(v0, 0.f); v0 *= v0;
                    v1 = fmaxf(v1, 0.f); v1 *= v1;
                    v2 = fmaxf(v2, 0.f); v2 *= v2;
                    v3 = fmaxf(v3, 0.f); v3 *= v3;
                }
                if (outH) {
                    __half2 lo = __floats2half2_rn(v0, v1);
                    __half2 hi = __floats2half2_rn(v2, v3);
                    *(uint32_t*)((__half*)C + (size_t) r      * Ntot + c) = *(uint32_t*)&lo;
                    *(uint32_t*)((__half*)C + (size_t)(r + 8) * Ntot + c) = *(uint32_t*)&hi;
                } else {
                    float2 lo; lo.x = v0; lo.y = v1;
                    float2 hi; hi.x = v2; hi.y = v3;
                    *(float2*)((float*)C + (size_t) r      * Ntot + c) = lo;
                    *(float2*)((float*)C + (size_t)(r + 8) * Ntot + c) = hi;
                }
            }
        }

        __threadfence();
        __syncthreads();
        if (tid == 0) atomicAdd(doneCnt, 1);
    }

    // ---- combine ----
    if (tid == 0) {
        while (atomicAdd(&g_done_dn, 0) < N_DN) __nanosleep(64);
        __threadfence();
    }
    __syncthreads();

    for (int t = blockIdx.x; t < T_TOK; t += gridDim.x) {
        int h = tid * 4;
        float4 o = *(const float4*)&g_ys[(size_t)t * HDIM + h];
        #pragma unroll
        for (int j = 0; j < TOPK; j++) {
            int slot = g_slotmap[t*TOPK + j];
            float w = g_topw[t*TOPK + j];
            float4 v = *(const float4*)&g_y[(size_t)slot * HDIM + h];
            o.x += w * v.x; o.y += w * v.y; o.z += w * v.z; o.w += w * v.w;
        }
        *(float4*)&out[(size_t)t * HDIM + h] = o;
    }
}

// ---------------- launch ----------------
extern "C" void kernel_launch(void* const* d_in, const int* in_sizes, int n_in,
                              void* d_out, int out_size) {
    const float *x = 0, *Wg = 0, *bias = 0, *W1 = 0, *W2 = 0, *Ws1 = 0, *Ws2 = 0;
    for (int i = 0; i < n_in; i++) {
        int sz = in_sizes[i];
        const float* p = (const float*)d_in[i];
        if      (sz == 2097152) { x = p; }
        else if (sz == 16384)   { Wg = p; }
        else if (sz == 16)      { bias = p; }
        else if (sz == 8388608) { if (!W1) W1 = p; else W2 = p; }
        else if (sz == 1048576) { if (!Ws1) Ws1 = p; else Ws2 = p; }
    }
    if (!x || !Wg || !bias || !W1 || !W2 || !Ws1 || !Ws2) {
        x = (const float*)d_in[0]; Wg = (const float*)d_in[1]; bias = (const float*)d_in[2];
        W1 = (const float*)d_in[3]; W2 = (const float*)d_in[4];
        Ws1 = (const float*)d_in[5]; Ws2 = (const float*)d_in[6];
    }
    float* out = (float*)d_out;

    cudaFuncSetAttribute(moe_persistent, cudaFuncAttributeMaxDynamicSharedMemorySize, SMEM_TOTAL);

    int smCount = 148, occ = 1;
    cudaDeviceGetAttribute(&smCount, cudaDevAttrMultiProcessorCount, 0);
    cudaOccupancyMaxActiveBlocksPerMultiprocessor(&occ, moe_persistent, 256, SMEM_TOTAL);
    if (occ < 1) occ = 1;
    int grid = smCount * occ;

    init_cvt<<<2048, 256>>>(x, W1, W2, Ws1, Ws2);     // 1: state reset + fp16 cvt
    router_kernel<<<T_TOK, 128>>>(x, Wg, bias);        // 2
    scan_fill<<<1, 256>>>();                           // 3
    moe_persistent<<<grid, 256, SMEM_TOTAL>>>(out);    // 4
}

// round 16
// speedup vs baseline: 1.8533x; 1.0185x over previous
#include <cuda_runtime.h>
#include <cuda_fp16.h>
#include <math.h>
#include <stdint.h>

// Problem constants
#define T_TOK   2048
#define HDIM    1024
#define NEXP    16
#define IDIM    512
#define ISDIM   1024
#define TOPK    4
#define NGRP    4
#define EPG     4
#define SCALE_F 2.5f

#define BM 128
#define BN 128
#define BK 32
#define MAXSLOTS (8192 + NEXP*BM)    // 10240
#define SMS 40
#define TILEH (128 * SMS)
#define STAGE_BYTES (TILEH * 2)
#define NSTAGE 4
#define SMEM_TOTAL (2 * NSTAGE * STAGE_BYTES)   // 81920 B

// tile counts
#define N_EU 320
#define N_SU 128
#define N_ED 640
#define N_SD 128
#define NTILES (N_EU + N_SU + N_ED + N_SD)   // 1216
#define N_DN  (N_ED + N_SD)                  // 768

// cvt segmentation (float4 units)
#define C_X   524288u
#define C_W1  2097152u
#define C_W2  2097152u
#define C_WS  262144u
#define C_TOT (C_X + C_W1 + C_W2 + 2*C_WS)   // 5242880

// ---------------- scratch ----------------
__device__ float  g_topw[T_TOK*TOPK];
__device__ int    g_tope[T_TOK*TOPK];
__device__ int    g_slotmap[T_TOK*TOPK];
__device__ int    g_list[MAXSLOTS];
__device__ int    g_off[NEXP+1];

__device__ int    g_tix;
__device__ int    g_done_eu[80];
__device__ int    g_done_su[16];
__device__ int    g_done_dn;

__device__ __half h_x  [(size_t)T_TOK * HDIM];
__device__ __half h_W1 [(size_t)NEXP * IDIM * HDIM];
__device__ __half h_W2 [(size_t)NEXP * HDIM * IDIM];
__device__ __half h_Ws1[(size_t)ISDIM * HDIM];
__device__ __half h_Ws2[(size_t)HDIM * ISDIM];

__device__ __half g_hid[(size_t)MAXSLOTS * IDIM];
__device__ float  g_y  [(size_t)MAXSLOTS * HDIM];
__device__ __half g_hs [(size_t)T_TOK * ISDIM];
__device__ float  g_ys [(size_t)T_TOK * HDIM];

// ---------------- helpers ----------------
__device__ __forceinline__ uint32_t smem_u32(const void* p) {
    uint32_t a;
    asm("{ .reg .u64 t; cvta.to.shared.u64 t, %1; cvt.u32.u64 %0, t; }" : "=r"(a) : "l"(p));
    return a;
}
__device__ __forceinline__ void cp16(uint32_t dst, const void* src) {
    asm volatile("cp.async.cg.shared.global [%0], [%1], 16;" :: "r"(dst), "l"(src));
}
__device__ __forceinline__ void ldsm_x4(uint32_t* r, uint32_t addr) {
    asm volatile("ldmatrix.sync.aligned.m8n8.x4.shared.b16 {%0,%1,%2,%3}, [%4];"
                 : "=r"(r[0]), "=r"(r[1]), "=r"(r[2]), "=r"(r[3]) : "r"(addr));
}
__device__ __forceinline__ void mma_f16(float* c, const uint32_t* a, const uint32_t* b) {
    asm volatile(
        "mma.sync.aligned.m16n8k16.row.col.f32.f16.f16.f32 "
        "{%0,%1,%2,%3}, {%4,%5,%6,%7}, {%8,%9}, {%0,%1,%2,%3};"
        : "+f"(c[0]), "+f"(c[1]), "+f"(c[2]), "+f"(c[3])
        : "r"(a[0]), "r"(a[1]), "r"(a[2]), "r"(a[3]), "r"(b[0]), "r"(b[1]));
}

// ---------------- cvt + router (one kernel, 2048 blocks x 256) ----------------
// Block b: (a) routes token b (writes g_tope/g_topw only; no global atomics),
//          (b) grid-stride fp32->fp16 conversion of all operands.
__global__ void cvt_router(const float* __restrict__ x,  const float* __restrict__ W1,
                           const float* __restrict__ W2, const float* __restrict__ Ws1,
                           const float* __restrict__ Ws2, const float* __restrict__ Wg,
                           const float* __restrict__ bias) {
    __shared__ float sx[HDIM];
    __shared__ float slog[NEXP];
    int tid  = threadIdx.x;
    int lane = tid & 31;
    int warp = tid >> 5;
    int t = blockIdx.x;

    // ---- route token t ----
    if (t < T_TOK) {
        const float* xr = x + (size_t)t * HDIM;
        for (int i = tid; i < HDIM; i += 256) sx[i] = xr[i];
        __syncthreads();
        #pragma unroll
        for (int eo = 0; eo < 2; eo++) {
            int e = warp * 2 + eo;
            const float* w = Wg + (size_t)e * HDIM;
            float p = 0.f;
            for (int i = lane; i < HDIM; i += 32) p += sx[i] * w[i];
            #pragma unroll
            for (int o = 16; o; o >>= 1) p += __shfl_xor_sync(0xffffffffu, p, o);
            if (lane == 0) slog[e] = p;
        }
        __syncthreads();
        if (tid == 0) {
            float sc[NEXP], ch[NEXP];
            #pragma unroll
            for (int e = 0; e < NEXP; e++) {
                sc[e] = 1.f / (1.f + expf(-slog[e]));
                ch[e] = sc[e] + bias[e];
            }
            float gs[NGRP];
            #pragma unroll
            for (int g = 0; g < NGRP; g++) {
                float m1 = -1e30f, m2 = -1e30f;
                #pragma unroll
                for (int k = 0; k < EPG; k++) {
                    float v = ch[g*EPG + k];
                    if (v > m1) { m2 = m1; m1 = v; } else if (v > m2) { m2 = v; }
                }
                gs[g] = m1 + m2;
            }
            int g1 = 0;
            for (int g = 1; g < NGRP; g++) if (gs[g] > gs[g1]) g1 = g;
            int g2 = -1;
            for (int g = 0; g < NGRP; g++) { if (g == g1) continue; if (g2 < 0 || gs[g] > gs[g2]) g2 = g; }
            float masked[NEXP];
            #pragma unroll
            for (int e = 0; e < NEXP; e++) {
                int g = e >> 2;
                masked[e] = (g == g1 || g == g2) ? ch[e] : 0.f;
            }
            int idx[TOPK]; float tw[TOPK]; float wsum = 0.f;
            #pragma unroll
            for (int j = 0; j < TOPK; j++) {
                int b = 0;
                for (int e = 1; e < NEXP; e++) if (masked[e] > masked[b]) b = e;
                idx[j] = b; tw[j] = sc[b]; wsum += sc[b];
                masked[b] = -1e30f;
            }
            float inv = SCALE_F / (wsum + 1e-20f);
            #pragma unroll
            for (int j = 0; j < TOPK; j++) {
                g_topw[t*TOPK + j] = tw[j] * inv;
                g_tope[t*TOPK + j] = idx[j];
            }
        }
    }

    // ---- fp32 -> fp16 conversion (grid-stride) ----
    uint32_t gi = blockIdx.x * 256 + tid;
    uint32_t stride = gridDim.x * 256;
    for (uint32_t i = gi; i < C_TOT; i += stride) {
        const float* s; __half* d; uint32_t off;
        if      (i < C_X)                      { s = x;   d = h_x;   off = i; }
        else if (i < C_X + C_W1)               { s = W1;  d = h_W1;  off = i - C_X; }
        else if (i < C_X + C_W1 + C_W2)        { s = W2;  d = h_W2;  off = i - C_X - C_W1; }
        else if (i < C_X + C_W1 + C_W2 + C_WS) { s = Ws1; d = h_Ws1; off = i - C_X - C_W1 - C_W2; }
        else                                   { s = Ws2; d = h_Ws2; off = i - C_X - C_W1 - C_W2 - C_WS; }
        float4 v = *(const float4*)(s + (size_t)off * 4);
        __half2 lo = __floats2half2_rn(v.x, v.y);
        __half2 hi = __floats2half2_rn(v.z, v.w);
        uint2 u; u.x = *(uint32_t*)&lo; u.y = *(uint32_t*)&hi;
        *(uint2*)(d + (size_t)off * 4) = u;
    }
}

// ---------------- fill16: per-expert compaction + offsets + state reset ----------------
// Block e: count all experts from g_tope, derive own offset locally, assign slots
// for expert e, write pad -1s, write g_off[e] (+ g_off[16] by block 15).
// Block 0 additionally resets queue/done counters (runs before moe_persistent).
__global__ void fill16() {
    __shared__ int s_cnt[NEXP];
    __shared__ int s_cur;
    int e = blockIdx.x;
    int tid = threadIdx.x;

    if (tid < NEXP) s_cnt[tid] = 0;
    if (tid == 0) s_cur = 0;
    __syncthreads();

    // pass 1: count all experts
    for (int i = tid; i < T_TOK * TOPK; i += 256)
        atomicAdd(&s_cnt[g_tope[i]], 1);
    __syncthreads();

    // local prefix of padded counts
    int off = 0;
    #pragma unroll
    for (int q = 0; q < NEXP; q++) {
        int padded = ((s_cnt[q] + BM - 1) / BM) * BM;
        if (q < e) off += padded;
    }
    int myCnt = s_cnt[e];
    int myPad = ((myCnt + BM - 1) / BM) * BM;

    if (tid == 0) {
        g_off[e] = off;
        if (e == NEXP - 1) g_off[NEXP] = off + myPad;
    }

    // state resets (block 0; safely before moe_persistent launch)
    if (e == 0) {
        if (tid == 0) { g_tix = 0; g_done_dn = 0; }
        if (tid < 80) g_done_eu[tid] = 0;
        if (tid < 16) g_done_su[tid] = 0;
    }

    // pass 2: assign slots for expert e
    for (int t = tid; t < T_TOK; t += 256) {
        #pragma unroll
        for (int j = 0; j < TOPK; j++) {
            if (g_tope[t*TOPK + j] == e) {
                int pos = atomicAdd(&s_cur, 1);
                int slot = off + pos;
                g_list[slot] = t;
                g_slotmap[t*TOPK + j] = slot;
            }
        }
    }
    __syncthreads();

    // pad region -> -1
    for (int i = myCnt + tid; i < myPad; i += 256)
        g_list[off + i] = -1;
}

// ---------------- persistent MoE kernel: 4 GEMMs + combine (UNCHANGED from R15) ----------------
__global__ void __launch_bounds__(256)
moe_persistent(float* __restrict__ out) {
    extern __shared__ __align__(16) __half dsm[];
    __shared__ int s_tix;

    int tid  = threadIdx.x;
    int lane = tid & 31;
    int warp = tid >> 5;
    int wm = (warp & 1) * 64;
    int wn = (warp >> 1) * 32;

    uint32_t s0 = smem_u32(dsm);
    uint32_t aB[NSTAGE], bB[NSTAGE];
    #pragma unroll
    for (int s = 0; s < NSTAGE; s++) {
        aB[s] = s0 + s * STAGE_BYTES;
        bB[s] = s0 + (NSTAGE + s) * STAGE_BYTES;
    }

    int lrow = tid >> 1;
    int lcol = (tid & 1) * 16;
    uint32_t dOff = (uint32_t)(lrow * SMS + lcol) * 2;
    uint32_t aOff = (uint32_t)((wm + (lane & 15)) * SMS + (lane >> 4) * 8) * 2;
    uint32_t bOff = (uint32_t)((wn + ((lane >> 4) * 8) + (lane & 7)) * SMS + ((lane >> 3) & 1) * 8) * 2;

    while (true) {
        if (tid == 0) s_tix = atomicAdd(&g_tix, 1);
        __syncthreads();
        int tix = s_tix;
        if (tix >= NTILES) break;

        const __half *A, *W;
        void* C;
        int K, Ntot, relu, outH, gather;
        int row0, n0;
        int* doneCnt;
        int* waitCnt = 0; int waitNeed = 0;
        bool skip = false;

        if (tix < N_EU) {
            int rb = tix >> 2, bn = tix & 3;
            row0 = rb * BM; n0 = bn * BN;
            A = h_x; gather = 1; K = HDIM; Ntot = IDIM;
            C = (void*)g_hid; relu = 1; outH = 1;
            doneCnt = &g_done_eu[rb];
            W = h_W1;
            int tot = g_off[NEXP];
            if (row0 >= tot) skip = true;
            else {
                int eid = 0;
                while (row0 >= g_off[eid+1]) eid++;
                W = h_W1 + (size_t)eid * IDIM * HDIM;
            }
        } else if (tix < N_EU + N_SU) {
            int i2 = tix - N_EU; int rb = i2 >> 3, bn = i2 & 7;
            row0 = rb * BM; n0 = bn * BN;
            A = h_x; gather = 0; W = h_Ws1; K = HDIM; Ntot = ISDIM;
            C = (void*)g_hs; relu = 1; outH = 1;
            doneCnt = &g_done_su[rb];
        } else if (tix < N_EU + N_SU + N_ED) {
            int i2 = tix - N_EU - N_SU; int rb = i2 >> 3, bn = i2 & 7;
            row0 = rb * BM; n0 = bn * BN;
            A = g_hid; gather = 0; K = IDIM; Ntot = HDIM;
            C = (void*)g_y; relu = 0; outH = 0;
            doneCnt = &g_done_dn;
            W = h_W2;
            int tot = g_off[NEXP];
            if (row0 >= tot) skip = true;
            else {
                int eid = 0;
                while (row0 >= g_off[eid+1]) eid++;
                W = h_W2 + (size_t)eid * HDIM * IDIM;
                waitCnt = &g_done_eu[rb]; waitNeed = 4;
            }
        } else {
            int i2 = tix - N_EU - N_SU - N_ED; int rb = i2 >> 3, bn = i2 & 7;
            row0 = rb * BM; n0 = bn * BN;
            A = g_hs; gather = 0; W = h_Ws2; K = ISDIM; Ntot = HDIM;
            C = (void*)g_ys; relu = 0; outH = 0;
            doneCnt = &g_done_dn;
            waitCnt = &g_done_su[rb]; waitNeed = 8;
        }

        if (skip) {
            if (tid == 0) atomicAdd(doneCnt, 1);
            continue;
        }
        if (waitCnt) {
            if (tid == 0) {
                while (atomicAdd(waitCnt, 0) < waitNeed) __nanosleep(64);
                __threadfence();
            }
            __syncthreads();
        }

        const __half* arow;
        if (gather) {
            int tok = g_list[row0 + lrow];
            arow = A + (size_t)(tok >= 0 ? tok : 0) * K;
        } else {
            arow = A + (size_t)(row0 + lrow) * K;
        }
        const __half* brow = W + (size_t)(n0 + lrow) * K;

        float acc[4][4][4];
        #pragma unroll
        for (int i = 0; i < 4; i++)
            #pragma unroll
            for (int j = 0; j < 4; j++)
                #pragma unroll
                for (int q = 0; q < 4; q++) acc[i][j][q] = 0.f;

        int nt = K / BK;

        #pragma unroll
        for (int p = 0; p < 3; p++) {
            if (p < nt) {
                const __half* as = arow + p * BK + lcol;
                const __half* bs = brow + p * BK + lcol;
                cp16(aB[p] + dOff,      as);
                cp16(aB[p] + dOff + 16, as + 8);
                cp16(bB[p] + dOff,      bs);
                cp16(bB[p] + dOff + 16, bs + 8);
                asm volatile("cp.async.commit_group;");
            }
        }

        for (int kt = 0; kt < nt; kt++) {
            if (kt + 3 <= nt)       asm volatile("cp.async.wait_group 2;");
            else if (kt + 2 <= nt)  asm volatile("cp.async.wait_group 1;");
            else                    asm volatile("cp.async.wait_group 0;");
            __syncthreads();

            if (kt + 3 < nt) {
                int s = (kt + 3) % NSTAGE;
                const __half* as = arow + (kt + 3) * BK + lcol;
                const __half* bs = brow + (kt + 3) * BK + lcol;
                cp16(aB[s] + dOff,      as);
                cp16(aB[s] + dOff + 16, as + 8);
                cp16(bB[s] + dOff,      bs);
                cp16(bB[s] + dOff + 16, bs + 8);
                asm volatile("cp.async.commit_group;");
            }

            int buf = kt % NSTAGE;
            uint32_t aT = aB[buf], bT = bB[buf];
            #pragma unroll
            for (int ks = 0; ks < 2; ks++) {
                uint32_t kkB = (uint32_t)(ks * 16) * 2;
                uint32_t af[4][4], bf[4][2];
                #pragma unroll
                for (int mf = 0; mf < 4; mf++)
                    ldsm_x4(af[mf], aT + aOff + (uint32_t)(mf * 16 * SMS) * 2 + kkB);
                #pragma unroll
                for (int nfp = 0; nfp < 2; nfp++) {
                    uint32_t r[4];
                    ldsm_x4(r, bT + bOff + (uint32_t)(nfp * 16 * SMS) * 2 + kkB);
                    bf[nfp*2+0][0] = r[0]; bf[nfp*2+0][1] = r[1];
                    bf[nfp*2+1][0] = r[2]; bf[nfp*2+1][1] = r[3];
                }
                #pragma unroll
                for (int mf = 0; mf < 4; mf++)
                    #pragma unroll
                    for (int nf = 0; nf < 4; nf++)
                        mma_f16(acc[mf][nf], af[mf], bf[nf]);
            }
        }

        int gq = lane >> 2;
        int c2 = (lane & 3) * 2;
        #pragma unroll
        for (int mf = 0; mf < 4; mf++) {
            int r = row0 + wm + mf * 16 + gq;
            #pragma unroll
            for (int nf = 0; nf < 4; nf++) {
                int c = n0 + wn + nf * 8 + c2;
                float v0 = acc[mf][nf][0], v1 = acc[mf][nf][1];
                float v2 = acc[mf][nf][2], v3 = acc[mf][nf][3];
                if (relu) {
                    v0 = fmaxf(v0, 0.f); v0 *= v0;
                    v1 = fmaxf(v1, 0.f); v1 *= v1;
                    v2 = fmaxf(v2, 0.f); v2 *= v2;
                    v3 = fmaxf(v3, 0.f); v3 *= v3;
                }
                if (outH) {
                    __half2 lo = __floats2half2_rn(v0, v1);
                    __half2 hi = __floats2half2_rn(v2, v3);
                    *(uint32_t*)((__half*)C + (size_t) r      * Ntot + c) = *(uint32_t*)&lo;
                    *(uint32_t*)((__half*)C + (size_t)(r + 8) * Ntot + c) = *(uint32_t*)&hi;
                } else {
                    float2 lo; lo.x = v0; lo.y = v1;
                    float2 hi; hi.x = v2; hi.y = v3;
                    *(float2*)((float*)C + (size_t) r      * Ntot + c) = lo;
                    *(float2*)((float*)C + (size_t)(r + 8) * Ntot + c) = hi;
                }
            }
        }

        __threadfence();
        __syncthreads();
        if (tid == 0) atomicAdd(doneCnt, 1);
    }

    // ---- combine ----
    if (tid == 0) {
        while (atomicAdd(&g_done_dn, 0) < N_DN) __nanosleep(64);
        __threadfence();
    }
    __syncthreads();

    for (int t = blockIdx.x; t < T_TOK; t += gridDim.x) {
        int h = tid * 4;
        float4 o = *(const float4*)&g_ys[(size_t)t * HDIM + h];
        #pragma unroll
        for (int j = 0; j < TOPK; j++) {
            int slot = g_slotmap[t*TOPK + j];
            float w = g_topw[t*TOPK + j];
            float4 v = *(const float4*)&g_y[(size_t)slot * HDIM + h];
            o.x += w * v.x; o.y += w * v.y; o.z += w * v.z; o.w += w * v.w;
        }
        *(float4*)&out[(size_t)t * HDIM + h] = o;
    }
}

// ---------------- launch ----------------
extern "C" void kernel_launch(void* const* d_in, const int* in_sizes, int n_in,
                              void* d_out, int out_size) {
    const float *x = 0, *Wg = 0, *bias = 0, *W1 = 0, *W2 = 0, *Ws1 = 0, *Ws2 = 0;
    for (int i = 0; i < n_in; i++) {
        int sz = in_sizes[i];
        const float* p = (const float*)d_in[i];
        if      (sz == 2097152) { x = p; }
        else if (sz == 16384)   { Wg = p; }
        else if (sz == 16)      { bias = p; }
        else if (sz == 8388608) { if (!W1) W1 = p; else W2 = p; }
        else if (sz == 1048576) { if (!Ws1) Ws1 = p; else Ws2 = p; }
    }
    if (!x || !Wg || !bias || !W1 || !W2 || !Ws1 || !Ws2) {
        x = (const float*)d_in[0]; Wg = (const float*)d_in[1]; bias = (const float*)d_in[2];
        W1 = (const float*)d_in[3]; W2 = (const float*)d_in[4];
        Ws1 = (const float*)d_in[5]; Ws2 = (const float*)d_in[6];
    }
    float* out = (float*)d_out;

    cudaFuncSetAttribute(moe_persistent, cudaFuncAttributeMaxDynamicSharedMemorySize, SMEM_TOTAL);

    int smCount = 148, occ = 1;
    cudaDeviceGetAttribute(&smCount, cudaDevAttrMultiProcessorCount, 0);
    cudaOccupancyMaxActiveBlocksPerMultiprocessor(&occ, moe_persistent, 256, SMEM_TOTAL);
    if (occ < 1) occ = 1;
    int grid = smCount * occ;

    cvt_router<<<2048, 256>>>(x, W1, W2, Ws1, Ws2, Wg, bias);   // 1
    fill16<<<NEXP, 256>>>();                                    // 2
    moe_persistent<<<grid, 256, SMEM_TOTAL>>>(out);             // 3
}